// round 10
// baseline (speedup 1.0000x reference)
#include <cuda_runtime.h>

#define NN   4096
#define TT   300
#define TW   10
#define NBLK 128
#define NT1  256
#define NT2  512

// ---------------- device scratch ----------------
__device__ unsigned g_mask[NN * TW];
__device__ float    g_Xpart[4ull * 320 * NN];
__device__ __align__(256) unsigned long long g_slot[TT][NBLK];   // {tag=t+1, mask}

__device__ __forceinline__ unsigned long long ldcg64(const unsigned long long* p) {
    unsigned long long v; asm volatile("ld.global.cg.b64 %0, [%1];" : "=l"(v) : "l"(p)); return v;
}
__device__ __forceinline__ void stcg64(unsigned long long* p, unsigned long long v) {
    asm volatile("st.global.cg.b64 [%0], %1;" :: "l"(p), "l"(v));
}
__device__ __forceinline__ float4 ldcg128(const float* p) {
    float4 v;
    asm volatile("ld.global.cg.v4.f32 {%0,%1,%2,%3}, [%4];"
                 : "=f"(v.x), "=f"(v.y), "=f"(v.z), "=f"(v.w) : "l"(p));
    return v;
}

// ---------------- kernel 1: pack inp bits + clear slot tags ----------------
__global__ void __launch_bounds__(256) pack_kernel(const int* __restrict__ inp) {
    const int blk  = blockIdx.x;
    const int word = blk % TW;
    const int i    = (blk / TW) * 256 + threadIdx.x;
    unsigned m = 0u;
    const int tb = word * 32;
    #pragma unroll
    for (int b = 0; b < 32; ++b) {
        int t = tb + b;
        if (t < TT) m |= (((unsigned)inp[(size_t)t * NN + i]) & 1u) << b;
    }
    g_mask[i * TW + word] = m;
    int gid = blk * 256 + threadIdx.x;
    if (gid < TT * NBLK) ((unsigned long long*)g_slot)[gid] = 0ull;
}

// ---------------- kernel 2: X partials via packed f32x2 FFMA (exact) ----------
__global__ void __launch_bounds__(NT1) xgemm_kernel(const float* __restrict__ w) {
    __shared__ unsigned long long Adup[128][18];
    const int tid  = threadIdx.x;
    const int tile = blockIdx.x;
    int word = tile % 10;
    int ccq  = tile / 10;
    int cc   = ccq >> 2;
    int q    = ccq & 3;
    int j    = cc * 256 + tid;
    int ibase = q * 1024;

    unsigned long long acc[16];
    #pragma unroll
    for (int k = 0; k < 16; ++k) acc[k] = 0ull;

    for (int sub = 0; sub < 8; ++sub) {
        int ib = ibase + sub * 128;
        __syncthreads();
        for (int e = tid; e < 2048; e += NT1) {
            int ii = e >> 4, tp = e & 15;
            unsigned m  = g_mask[(ib + ii) * TW + word];
            unsigned lo = (m >> (2 * tp))     & 1u ? 0x3f800000u : 0u;
            unsigned hi = (m >> (2 * tp + 1)) & 1u ? 0x3f800000u : 0u;
            Adup[ii][tp] = ((unsigned long long)hi << 32) | lo;
        }
        __syncthreads();
        for (int ii = 0; ii < 128; ++ii) {
            unsigned wu = __float_as_uint(w[(size_t)(ib + ii) * NN + j]);
            unsigned long long wpk;
            asm("mov.b64 %0, {%1, %1};" : "=l"(wpk) : "r"(wu));
            const ulonglong2* ap = (const ulonglong2*)(&Adup[ii][0]);
            #pragma unroll
            for (int k = 0; k < 8; ++k) {
                ulonglong2 a2 = ap[k];
                asm("fma.rn.f32x2 %0, %1, %2, %0;" : "+l"(acc[2*k])   : "l"(wpk), "l"(a2.x));
                asm("fma.rn.f32x2 %0, %1, %2, %0;" : "+l"(acc[2*k+1]) : "l"(wpk), "l"(a2.y));
            }
        }
    }
    #pragma unroll
    for (int tp = 0; tp < 16; ++tp) {
        int t0 = word * 32 + 2 * tp;
        g_Xpart[((size_t)q * 320 + t0)     * NN + j] = __uint_as_float((unsigned)acc[tp]);
        g_Xpart[((size_t)q * 320 + t0 + 1) * NN + j] = __uint_as_float((unsigned)(acc[tp] >> 32));
    }
}

// ---------------- kernel 3: persistent recurrent LIF (incremental gather) ----
// 16 warps x 8 slot words each. A warp gathers each word THE MOMENT it is
// published (overlapping the straggler wait), into per-word partials p[k];
// final combination is a fixed tree -> bit-exact determinism.
__global__ void __launch_bounds__(NT2, 1)
lif_kernel(const float* __restrict__ w_rec, float* __restrict__ out) {
    __shared__ float4 part4[16][8];        // per-warp column partials

    const int tid = threadIdx.x;
    const int bid = blockIdx.x;
    const int l   = tid & 31;
    const int wp  = tid >> 5;              // warp 0..15
    const int sub = l >> 3;                // row within 4-row wave
    const int ln8 = l & 7;                 // 16B chunk within 128B segment
    const int j0  = bid * 32;

    float v = 0.f, rt = 0.f, tl = 1.f;
    const float DECAY = 0.99004983374916805f;   // fp32(exp(-1/100))

    for (int t = 0; t < TT; ++t) {
        float x0 = 0.f, x1 = 0.f, x2 = 0.f, x3 = 0.f;
        if (wp == 0) {
            const int j = j0 + l;
            x0 = g_Xpart[(size_t)(0 * 320 + t) * NN + j];
            x1 = g_Xpart[(size_t)(1 * 320 + t) * NN + j];
            x2 = g_Xpart[(size_t)(2 * 320 + t) * NN + j];
            x3 = g_Xpart[(size_t)(3 * 320 + t) * NN + j];
        }

        float4 p[8];
        #pragma unroll
        for (int k = 0; k < 8; ++k) p[k] = make_float4(0.f, 0.f, 0.f, 0.f);

        if (t > 0) {
            const unsigned long long* slot = &g_slot[t - 1][8 * wp];
            const unsigned want = (unsigned)t;
            const float* wr = w_rec + j0 + (ln8 << 2);
            unsigned pend = 0xFFu;
            while (pend) {
                // re-poll only pending words (lane k<8 owns word 8*wp+k)
                unsigned long long u = 0ull;
                bool mine = (l < 8) && ((pend >> l) & 1u);
                if (mine) u = ldcg64(slot + l);
                bool hit = mine && ((unsigned)(u >> 32) == want);
                unsigned rdy = __ballot_sync(0xffffffffu, hit);
                unsigned lo32 = (unsigned)u;
                unsigned r = rdy;
                while (r) {           // gather each newly-ready word NOW
                    int k = __ffs(r) - 1; r &= r - 1u;
                    unsigned m = __shfl_sync(0xffffffffu, lo32, k);
                    int c = __popc(m);
                    float4 rv[8];
                    #pragma unroll
                    for (int u8 = 0; u8 < 8; ++u8) {
                        int kk = 4 * u8 + sub;
                        float4 z = make_float4(0.f, 0.f, 0.f, 0.f);
                        if (kk < c) {
                            size_t row = (size_t)(((8 * wp + k) << 5) + __fns(m, 0, kk + 1));
                            z = ldcg128(wr + (row << 12));
                        }
                        rv[u8] = z;
                    }
                    float4 ws;      // fixed-order wave sum (deterministic)
                    ws.x = ((rv[0].x + rv[1].x) + (rv[2].x + rv[3].x))
                         + ((rv[4].x + rv[5].x) + (rv[6].x + rv[7].x));
                    ws.y = ((rv[0].y + rv[1].y) + (rv[2].y + rv[3].y))
                         + ((rv[4].y + rv[5].y) + (rv[6].y + rv[7].y));
                    ws.z = ((rv[0].z + rv[1].z) + (rv[2].z + rv[3].z))
                         + ((rv[4].z + rv[5].z) + (rv[6].z + rv[7].z));
                    ws.w = ((rv[0].w + rv[1].w) + (rv[2].w + rv[3].w))
                         + ((rv[4].w + rv[5].w) + (rv[6].w + rv[7].w));
                    p[k] = ws;
                }
                pend &= ~rdy;
            }
        }

        // fixed-tree combine of the 8 word partials (arrival-order independent)
        float4 acc;
        acc.x = ((p[0].x + p[1].x) + (p[2].x + p[3].x)) + ((p[4].x + p[5].x) + (p[6].x + p[7].x));
        acc.y = ((p[0].y + p[1].y) + (p[2].y + p[3].y)) + ((p[4].y + p[5].y) + (p[6].y + p[7].y));
        acc.z = ((p[0].z + p[1].z) + (p[2].z + p[3].z)) + ((p[4].z + p[5].z) + (p[6].z + p[7].z));
        acc.w = ((p[0].w + p[1].w) + (p[2].w + p[3].w)) + ((p[4].w + p[5].w) + (p[6].w + p[7].w));
        // reduce the 4 sub-rows within the warp (fixed order)
        acc.x += __shfl_down_sync(0xffffffffu, acc.x, 16);
        acc.y += __shfl_down_sync(0xffffffffu, acc.y, 16);
        acc.z += __shfl_down_sync(0xffffffffu, acc.z, 16);
        acc.w += __shfl_down_sync(0xffffffffu, acc.w, 16);
        acc.x += __shfl_down_sync(0xffffffffu, acc.x, 8);
        acc.y += __shfl_down_sync(0xffffffffu, acc.y, 8);
        acc.z += __shfl_down_sync(0xffffffffu, acc.z, 8);
        acc.w += __shfl_down_sync(0xffffffffu, acc.w, 8);
        if (l < 8) part4[wp][ln8] = acc;
        __syncthreads();   // the ONLY per-step block barrier

        if (wp == 0) {
            const float* pf = (const float*)part4;   // [16][32 floats]
            float xr = 0.f;
            #pragma unroll
            for (int w16 = 0; w16 < 16; ++w16) xr += pf[w16 * 32 + l];
            float xt = xr + ((x0 + x1) + (x2 + x3));
            // LIF dynamics, exact reference order
            v *= DECAY;
            float xin = (rt > 0.f) ? 0.f : xt;
            rt -= 1.f;
            v += xin;
            bool sp = (v >= 10.f);
            if (sp) { tl = (float)t / 300.0f; rt = 1.f; v = 0.f; }

            unsigned ball = __ballot_sync(0xffffffffu, sp);
            if (t < TT - 1 && l == 0)
                stcg64(&g_slot[t][bid],
                       ((unsigned long long)(unsigned)(t + 1) << 32) |
                       (unsigned long long)ball);
            const int j = j0 + l;
            out[(size_t)t * NN + j]            = sp ? 1.f : 0.f;
            out[(size_t)(TT + t) * NN + j]     = tl;
            out[(size_t)(2 * TT + t) * NN + j] = v;
        }
        // WAR safety: gather warps write part4(t+1) only after their poll(t+1)
        // succeeds, which requires this block's publish(t), which happens after
        // warp 0 consumed part4(t). No second barrier needed.
    }
}

// ---------------- launch ----------------
extern "C" void kernel_launch(void* const* d_in, const int* in_sizes, int n_in,
                              void* d_out, int out_size) {
    const int* inp; const float* w; const float* w_rec;
    if (in_sizes[0] == TT * NN) {
        inp = (const int*)d_in[0]; w = (const float*)d_in[1]; w_rec = (const float*)d_in[2];
    } else if (n_in > 1 && in_sizes[1] == TT * NN) {
        inp = (const int*)d_in[1]; w = (const float*)d_in[0]; w_rec = (const float*)d_in[2];
    } else {
        inp = (const int*)d_in[2]; w = (const float*)d_in[0]; w_rec = (const float*)d_in[1];
    }
    float* out = (float*)d_out;

    pack_kernel<<<160, 256>>>(inp);
    xgemm_kernel<<<640, NT1>>>(w);
    lif_kernel<<<NBLK, NT2>>>(w_rec, out);
}

// round 11
// speedup vs baseline: 2.2477x; 2.2477x over previous
#include <cuda_runtime.h>

#define NN   4096
#define TT   300
#define TW   10
#define NBLK 128
#define NT1  256
#define NT2  512

// ---------------- device scratch ----------------
__device__ unsigned g_mask[NN * TW];
__device__ float    g_Xpart[4ull * 320 * NN];
__device__ __align__(256) unsigned long long g_slot[TT][NBLK];  // producers -> aggregator
__device__ __align__(256) unsigned long long g_rec[TT][NBLK];   // aggregator -> consumers
__device__ unsigned g_flag[TT];                                  // per-step ready flag

__device__ __forceinline__ void ldcgv2(const unsigned long long* p,
                                       unsigned long long& a, unsigned long long& b) {
    asm volatile("ld.global.cg.v2.u64 {%0,%1}, [%2];" : "=l"(a), "=l"(b) : "l"(p));
}
__device__ __forceinline__ void stcgv2(unsigned long long* p,
                                       unsigned long long a, unsigned long long b) {
    asm volatile("st.global.cg.v2.u64 [%0], {%1,%2};" :: "l"(p), "l"(a), "l"(b));
}
__device__ __forceinline__ void stcg64(unsigned long long* p, unsigned long long v) {
    asm volatile("st.global.cg.b64 [%0], %1;" :: "l"(p), "l"(v));
}
__device__ __forceinline__ unsigned ldcg32(const unsigned* p) {
    unsigned v; asm volatile("ld.global.cg.b32 %0, [%1];" : "=r"(v) : "l"(p)); return v;
}
__device__ __forceinline__ void stcg32(unsigned* p, unsigned v) {
    asm volatile("st.global.cg.b32 [%0], %1;" :: "l"(p), "r"(v));
}
__device__ __forceinline__ float4 ldcg128(const float* p) {
    float4 v;
    asm volatile("ld.global.cg.v4.f32 {%0,%1,%2,%3}, [%4];"
                 : "=f"(v.x), "=f"(v.y), "=f"(v.z), "=f"(v.w) : "l"(p));
    return v;
}

// ---------------- kernel 1: pack inp bits + clear sync state ----------------
__global__ void __launch_bounds__(256) pack_kernel(const int* __restrict__ inp) {
    const int blk  = blockIdx.x;
    const int word = blk % TW;
    const int i    = (blk / TW) * 256 + threadIdx.x;
    unsigned m = 0u;
    const int tb = word * 32;
    #pragma unroll
    for (int b = 0; b < 32; ++b) {
        int t = tb + b;
        if (t < TT) m |= (((unsigned)inp[(size_t)t * NN + i]) & 1u) << b;
    }
    g_mask[i * TW + word] = m;
    int gid = blk * 256 + threadIdx.x;
    if (gid < TT * NBLK) {
        ((unsigned long long*)g_slot)[gid] = 0ull;
        ((unsigned long long*)g_rec)[gid]  = 0ull;
    }
    if (gid < TT) g_flag[gid] = 0u;
}

// ---------------- kernel 2: X partials via packed f32x2 FFMA (exact) ----------
__global__ void __launch_bounds__(NT1) xgemm_kernel(const float* __restrict__ w) {
    __shared__ unsigned long long Adup[128][18];
    const int tid  = threadIdx.x;
    const int tile = blockIdx.x;
    int word = tile % 10;
    int ccq  = tile / 10;
    int cc   = ccq >> 2;
    int q    = ccq & 3;
    int j    = cc * 256 + tid;
    int ibase = q * 1024;

    unsigned long long acc[16];
    #pragma unroll
    for (int k = 0; k < 16; ++k) acc[k] = 0ull;

    for (int sub = 0; sub < 8; ++sub) {
        int ib = ibase + sub * 128;
        __syncthreads();
        for (int e = tid; e < 2048; e += NT1) {
            int ii = e >> 4, tp = e & 15;
            unsigned m  = g_mask[(ib + ii) * TW + word];
            unsigned lo = (m >> (2 * tp))     & 1u ? 0x3f800000u : 0u;
            unsigned hi = (m >> (2 * tp + 1)) & 1u ? 0x3f800000u : 0u;
            Adup[ii][tp] = ((unsigned long long)hi << 32) | lo;
        }
        __syncthreads();
        for (int ii = 0; ii < 128; ++ii) {
            unsigned wu = __float_as_uint(w[(size_t)(ib + ii) * NN + j]);
            unsigned long long wpk;
            asm("mov.b64 %0, {%1, %1};" : "=l"(wpk) : "r"(wu));
            const ulonglong2* ap = (const ulonglong2*)(&Adup[ii][0]);
            #pragma unroll
            for (int k = 0; k < 8; ++k) {
                ulonglong2 a2 = ap[k];
                asm("fma.rn.f32x2 %0, %1, %2, %0;" : "+l"(acc[2*k])   : "l"(wpk), "l"(a2.x));
                asm("fma.rn.f32x2 %0, %1, %2, %0;" : "+l"(acc[2*k+1]) : "l"(wpk), "l"(a2.y));
            }
        }
    }
    #pragma unroll
    for (int tp = 0; tp < 16; ++tp) {
        int t0 = word * 32 + 2 * tp;
        g_Xpart[((size_t)q * 320 + t0)     * NN + j] = __uint_as_float((unsigned)acc[tp]);
        g_Xpart[((size_t)q * 320 + t0 + 1) * NN + j] = __uint_as_float((unsigned)(acc[tp] >> 32));
    }
}

// ---------------- kernel 3: persistent recurrent LIF ---------------------------
// Blocks 0..127: LIF workers (identical to the 2137us kernel except the poll).
// Block 128: aggregator — the ONLY poller of g_slot; relays masks + raises flag.
__global__ void __launch_bounds__(NT2, 1)
lif_kernel(const float* __restrict__ w_rec, float* __restrict__ out) {
    __shared__ unsigned sh_mask[128];
    __shared__ int      sh_off[128];
    __shared__ int      sh_total;
    __shared__ int      sh_idx[NN];
    __shared__ float4   part4[16][9];

    const int tid = threadIdx.x;
    const int bid = blockIdx.x;
    const int l   = tid & 31;
    const int wp  = tid >> 5;

    // ================= aggregator block =================
    if (bid == NBLK) {
        if (wp != 0) return;
        for (int t = 0; t < TT - 1; ++t) {
            const unsigned long long* slot = &g_slot[t][4 * l];
            const unsigned want = (unsigned)(t + 1);
            unsigned long long a0, a1, b0, b1;
            bool okA = false, okB = false;
            while (1) {
                if (!okA) {
                    ldcgv2(slot, a0, a1);
                    okA = ((unsigned)(a0 >> 32) == want) & ((unsigned)(a1 >> 32) == want);
                }
                if (!okB) {
                    ldcgv2(slot + 2, b0, b1);
                    okB = ((unsigned)(b0 >> 32) == want) & ((unsigned)(b1 >> 32) == want);
                }
                if (__all_sync(0xffffffffu, okA & okB)) break;
            }
            // relay masks verbatim (tags included), then fence, then flag
            stcgv2(&g_rec[t][4 * l], a0, a1);
            stcgv2(&g_rec[t][4 * l + 2], b0, b1);
            __threadfence();
            __syncwarp();
            if (l == 0) {
                __threadfence();
                stcg32(&g_flag[t], want);
            }
        }
        return;
    }

    // ================= worker blocks =================
    const int sub = l >> 3;
    const int ln8 = l & 7;
    const int j0  = bid * 32;

    if (tid == 0) sh_total = 0;

    float v = 0.f, rt = 0.f, tl = 1.f;
    const float DECAY = 0.99004983374916805f;   // fp32(exp(-1/100))

    for (int t = 0; t < TT; ++t) {
        float x0 = 0.f, x1 = 0.f, x2 = 0.f, x3 = 0.f;
        if (wp == 0) {
            const int j = j0 + l;
            x0 = g_Xpart[(size_t)(0 * 320 + t) * NN + j];
            x1 = g_Xpart[(size_t)(1 * 320 + t) * NN + j];
            x2 = g_Xpart[(size_t)(2 * 320 + t) * NN + j];
            x3 = g_Xpart[(size_t)(3 * 320 + t) * NN + j];
            if (t > 0) {
                // poll ONE flag word (lane 0 only), then burst-read the record
                if (l == 0) {
                    while (ldcg32(&g_flag[t - 1]) != (unsigned)t) {}
                }
                __syncwarp();
                const unsigned long long* rec = &g_rec[t - 1][4 * l];
                const unsigned want = (unsigned)t;
                unsigned long long a0, a1, b0, b1;
                bool okA = false, okB = false;
                while (1) {          // tag-checked (first try should succeed)
                    if (!okA) {
                        ldcgv2(rec, a0, a1);
                        okA = ((unsigned)(a0 >> 32) == want) & ((unsigned)(a1 >> 32) == want);
                    }
                    if (!okB) {
                        ldcgv2(rec + 2, b0, b1);
                        okB = ((unsigned)(b0 >> 32) == want) & ((unsigned)(b1 >> 32) == want);
                    }
                    if (__all_sync(0xffffffffu, okA & okB)) break;
                }
                // scan in registers -> per-word offsets
                unsigned m0 = (unsigned)a0, m1 = (unsigned)a1;
                unsigned m2 = (unsigned)b0, m3 = (unsigned)b1;
                unsigned c0 = __popc(m0), c1 = __popc(m1);
                unsigned c2 = __popc(m2), c3 = __popc(m3);
                unsigned s4 = c0 + c1 + c2 + c3;
                unsigned incl = s4;
                #pragma unroll
                for (int d = 1; d < 32; d <<= 1) {
                    unsigned o = __shfl_up_sync(0xffffffffu, incl, d);
                    if (l >= d) incl += o;
                }
                if (l == 31) sh_total = (int)incl;
                unsigned excl = incl - s4;
                sh_mask[4 * l]     = m0;  sh_off[4 * l]     = (int)excl;
                sh_mask[4 * l + 1] = m1;  sh_off[4 * l + 1] = (int)(excl + c0);
                sh_mask[4 * l + 2] = m2;  sh_off[4 * l + 2] = (int)(excl + c0 + c1);
                sh_mask[4 * l + 3] = m3;  sh_off[4 * l + 3] = (int)(excl + c0 + c1 + c2);
            }
        }
        __syncthreads();   // S1a: masks + offsets ready

        if (t > 0 && tid < 128) {
            unsigned bits = sh_mask[tid];
            int o = sh_off[tid];
            int base = tid << 5;
            while (bits) {
                int b = __ffs(bits) - 1;
                bits &= bits - 1u;
                sh_idx[o++] = (base + b) << 12;    // row * NN
            }
        }
        __syncthreads();   // S1b: index list ready

        // gather: 4 rows per LDG.128 wave, batch of 8 waves in flight
        {
            const int S = sh_total;
            const float* wr = w_rec + j0 + (ln8 << 2);
            float4 acc = make_float4(0.f, 0.f, 0.f, 0.f);
            const int myrow = (wp << 2) + sub;
            for (int base = 0; base < S; base += 512) {
                float4 rv[8];
                #pragma unroll
                for (int u = 0; u < 8; ++u) {
                    int kk = base + (u << 6) + myrow;
                    float4 z = make_float4(0.f, 0.f, 0.f, 0.f);
                    if (kk < S) z = ldcg128(wr + sh_idx[kk]);
                    rv[u] = z;
                }
                #pragma unroll
                for (int u = 0; u < 8; ++u) {
                    acc.x += rv[u].x; acc.y += rv[u].y;
                    acc.z += rv[u].z; acc.w += rv[u].w;
                }
            }
            acc.x += __shfl_down_sync(0xffffffffu, acc.x, 16);
            acc.y += __shfl_down_sync(0xffffffffu, acc.y, 16);
            acc.z += __shfl_down_sync(0xffffffffu, acc.z, 16);
            acc.w += __shfl_down_sync(0xffffffffu, acc.w, 16);
            acc.x += __shfl_down_sync(0xffffffffu, acc.x, 8);
            acc.y += __shfl_down_sync(0xffffffffu, acc.y, 8);
            acc.z += __shfl_down_sync(0xffffffffu, acc.z, 8);
            acc.w += __shfl_down_sync(0xffffffffu, acc.w, 8);
            if (l < 8) part4[wp][ln8] = acc;
        }
        __syncthreads();   // S2: partials ready

        if (wp == 0) {
            const float* pf = (const float*)part4;   // row stride 36 floats
            float xr = 0.f;
            #pragma unroll
            for (int w16 = 0; w16 < 16; ++w16) xr += pf[w16 * 36 + l];
            float xt = xr + ((x0 + x1) + (x2 + x3));
            // LIF dynamics, exact reference order
            v *= DECAY;
            float xin = (rt > 0.f) ? 0.f : xt;
            rt -= 1.f;
            v += xin;
            bool sp = (v >= 10.f);
            if (sp) { tl = (float)t / 300.0f; rt = 1.f; v = 0.f; }

            unsigned ball = __ballot_sync(0xffffffffu, sp);
            if (t < TT - 1 && l == 0)
                stcg64(&g_slot[t][bid],
                       ((unsigned long long)(unsigned)(t + 1) << 32) |
                       (unsigned long long)ball);
            const int j = j0 + l;
            out[(size_t)t * NN + j]            = sp ? 1.f : 0.f;
            out[(size_t)(TT + t) * NN + j]     = tl;
            out[(size_t)(2 * TT + t) * NN + j] = v;
        }
    }
}

// ---------------- launch ----------------
extern "C" void kernel_launch(void* const* d_in, const int* in_sizes, int n_in,
                              void* d_out, int out_size) {
    const int* inp; const float* w; const float* w_rec;
    if (in_sizes[0] == TT * NN) {
        inp = (const int*)d_in[0]; w = (const float*)d_in[1]; w_rec = (const float*)d_in[2];
    } else if (n_in > 1 && in_sizes[1] == TT * NN) {
        inp = (const int*)d_in[1]; w = (const float*)d_in[0]; w_rec = (const float*)d_in[2];
    } else {
        inp = (const int*)d_in[2]; w = (const float*)d_in[0]; w_rec = (const float*)d_in[1];
    }
    float* out = (float*)d_out;

    pack_kernel<<<160, 256>>>(inp);
    xgemm_kernel<<<640, NT1>>>(w);
    lif_kernel<<<NBLK + 1, NT2>>>(w_rec, out);
}